// round 6
// baseline (speedup 1.0000x reference)
#include <cuda_runtime.h>
#include <cuda_fp16.h>
#include <cstdint>

#define C_IN    128
#define C_OUT   64
#define KOFF    27
#define M_PAIRS 100000
#define N_ROWS  100000
#define N_OUTP  200000
#define BN_EPS  1e-5f

// ---------------- device scratch (allocation-free) --------------------------
__device__ __half g_Xh[(size_t)N_ROWS * C_IN];      // 25.6 MB, L2-resident
__device__ uint4  g_Bfrag[KOFF * 8 * 4 * 32];       // 442 KB: MMA-ready B frags
__device__ float g_sum[C_OUT], g_sumsq[C_OUT];

// ---------------- PTX helpers ----------------------------------------------
__device__ __forceinline__ uint32_t smem_u32(const void* p) {
    uint32_t a;
    asm("{ .reg .u64 t; cvta.to.shared.u64 t, %1; cvt.u32.u64 %0, t; }" : "=r"(a) : "l"(p));
    return a;
}
#define BULK_CP(dst, src, bytes, mbar) \
    asm volatile("cp.async.bulk.shared::cluster.global.mbarrier::complete_tx::bytes " \
        "[%0], [%1], %2, [%3];" :: "r"(dst), "l"(src), "r"(bytes), "r"(mbar) : "memory")

#define MBAR_INIT(a, c) \
    asm volatile("mbarrier.init.shared.b64 [%0], %1;" :: "r"(a), "r"(c) : "memory")
#define MBAR_EXPECT_TX(a, tx) \
    asm volatile("mbarrier.arrive.expect_tx.shared.b64 _, [%0], %1;" :: "r"(a), "r"(tx) : "memory")
#define MBAR_WAIT(a, ph) do {                                                   \
    asm volatile("{ .reg .pred P; WL%=:"                                        \
        " mbarrier.try_wait.parity.acquire.cta.shared::cta.b64 P, [%0], %1, 0x989680;" \
        " @P bra.uni WD%=; bra.uni WL%=; WD%=: }"                               \
        :: "r"(a), "r"(ph) : "memory");                                         \
} while (0)

#define LDMATRIX_X4(r, addr) \
    asm volatile("ldmatrix.sync.aligned.m8n8.x4.shared.b16 {%0,%1,%2,%3}, [%4];" \
        : "=r"((r)[0]), "=r"((r)[1]), "=r"((r)[2]), "=r"((r)[3]) : "r"(addr))

#define MMA16816(d, a, b0, b1) \
    asm volatile("mma.sync.aligned.m16n8k16.row.col.f32.f16.f16.f32 " \
        "{%0,%1,%2,%3}, {%4,%5,%6,%7}, {%8,%9}, {%0,%1,%2,%3};" \
        : "+f"((d)[0]), "+f"((d)[1]), "+f"((d)[2]), "+f"((d)[3]) \
        : "r"((a)[0]), "r"((a)[1]), "r"((a)[2]), "r"((a)[3]), "r"(b0), "r"(b1))

// ---------------- convert x -> fp16 -----------------------------------------
__global__ void __launch_bounds__(256)
conv_x_kernel(const float* __restrict__ x)
{
    int idx = blockIdx.x * 256 + threadIdx.x;          // one per 4 floats
    if (idx >= N_ROWS * 32) return;
    float4 v = ((const float4*)x)[idx];
    __half2* dst = (__half2*)(g_Xh + (size_t)idx * 4);
    dst[0] = __floats2half2_rn(v.x, v.y);
    dst[1] = __floats2half2_rn(v.z, v.w);
}

// ---------------- build B fragments (MMA register layout) -------------------
// For (koff, kc, npair, lane): uint4 = {b0,b1} for nt=2*npair and nt=2*npair+1.
// b0(lane l) = half2{ W[ci0][co], W[ci0+1][co] },  b1 = same at ci0+8,
// where co = npair*16 + (l>>2) (+8 for odd nt), ci0 = kc*16 + (l&3)*2.
// Matches the ldmatrix-produced fragments of the R5 kernel bit-for-bit.
__global__ void __launch_bounds__(256)
bfrag_kernel(const float* __restrict__ w)
{
    int idx = blockIdx.x * 256 + threadIdx.x;
    if (idx < C_OUT) { g_sum[idx] = 0.f; g_sumsq[idx] = 0.f; }
    if (idx >= KOFF * 8 * 4 * 32) return;
    const int lane  = idx & 31;
    const int npair = (idx >> 5) & 3;
    const int kc    = (idx >> 7) & 7;
    const int ko    = idx >> 10;
    const int co    = npair * 16 + (lane >> 2);
    const int ci0   = kc * 16 + (lane & 3) * 2;
    const float* wk = w + (size_t)ko * (C_IN * C_OUT);
    __half2 b0e = __floats2half2_rn(wk[ ci0      * C_OUT + co],     wk[(ci0 + 1) * C_OUT + co]);
    __half2 b1e = __floats2half2_rn(wk[(ci0 + 8) * C_OUT + co],     wk[(ci0 + 9) * C_OUT + co]);
    __half2 b0o = __floats2half2_rn(wk[ ci0      * C_OUT + co + 8], wk[(ci0 + 1) * C_OUT + co + 8]);
    __half2 b1o = __floats2half2_rn(wk[(ci0 + 8) * C_OUT + co + 8], wk[(ci0 + 9) * C_OUT + co + 8]);
    g_Bfrag[idx] = make_uint4(*(uint32_t*)&b0e, *(uint32_t*)&b1e,
                              *(uint32_t*)&b0o, *(uint32_t*)&b1o);
}

// ---------------- fused gather(bulk) + HMMA + direct-frag scatter -----------
// grid = (521 pair-blocks, 27 offsets); block = 192 threads (6 warps).
// Tile: 192 pairs x 64 out-channels, K = 128. Warp w owns rows [32w, 32w+32).
// A only in smem (272B rows -> conflict-free ldmatrix); B comes from g_Bfrag
// via coalesced LDG.128 (L1-hot, 16 KB per k, shared by all CTAs of that k).
#define PAIRS_BLK 192
#define ROWB      272
#define SM_MBAR0  0
#define SM_MBAR1  8
#define SM_A      32
#define SMEM_FUSED (SM_A + PAIRS_BLK * ROWB)    // 52256

__global__ void __launch_bounds__(PAIRS_BLK, 4)
fused_kernel(const int* __restrict__ in_map,
             const int* __restrict__ out_map,
             float* __restrict__ out)
{
    extern __shared__ char smem[];
    const uint32_t sbase = smem_u32(smem);
    const uint32_t abase = sbase + SM_A;

    const int t    = threadIdx.x;
    const int lane = t & 31;
    const int w    = t >> 5;
    const int k    = blockIdx.y;

    // ---- pair indices (thread t owns pair-row t) ----
    const int p     = blockIdx.x * PAIRS_BLK + t;
    const int valid = (p < M_PAIRS);
    const int pc    = valid ? p : (M_PAIRS - 1);
    const int im    = in_map [k * M_PAIRS + pc];
    const int om    = valid ? out_map[k * M_PAIRS + pc] : -1;

    if (t == 0) { MBAR_INIT(sbase + SM_MBAR0, 1); MBAR_INIT(sbase + SM_MBAR1, 1); }
    __syncthreads();
    if (t == 0) MBAR_EXPECT_TX(sbase + SM_MBAR0, 96 * 256);
    if (t == 1) MBAR_EXPECT_TX(sbase + SM_MBAR1, 96 * 256);

    // ---- gather A: one 256B bulk per row ----
    const uint32_t mybar = sbase + (t < 96 ? SM_MBAR0 : SM_MBAR1);
    BULK_CP(abase + t * ROWB, g_Xh + (size_t)im * C_IN, 256, mybar);

    MBAR_WAIT(sbase + SM_MBAR0, 0);
    if (w >= 3) MBAR_WAIT(sbase + SM_MBAR1, 0);

    // ---- MMA mainloop: warp w owns rows [32w, 32w+32), cols 0..63 ----
    float d[2][8][4];
    #pragma unroll
    for (int mt = 0; mt < 2; ++mt)
        #pragma unroll
        for (int nt = 0; nt < 8; ++nt)
            #pragma unroll
            for (int j = 0; j < 4; ++j) d[mt][nt][j] = 0.f;

    const uint4* __restrict__ bfk = g_Bfrag + (size_t)k * (8 * 4 * 32) + lane;

    #pragma unroll
    for (int kc = 0; kc < 8; ++kc) {
        uint32_t a_frag[2][4];
        #pragma unroll
        for (int mt = 0; mt < 2; ++mt) {
            int row = w * 32 + mt * 16 + (lane & 15);
            int ch  = kc * 2 + (lane >> 4);
            LDMATRIX_X4(a_frag[mt], abase + row * ROWB + ch * 16);
        }
        #pragma unroll
        for (int np = 0; np < 4; ++np) {
            const uint4 q = __ldg(bfk + (kc * 4 + np) * 32);
            #pragma unroll
            for (int mt = 0; mt < 2; ++mt) {
                MMA16816(d[mt][2 * np],     a_frag[mt], q.x, q.y);
                MMA16816(d[mt][2 * np + 1], a_frag[mt], q.z, q.w);
            }
        }
    }

    // ---- scatter-add straight from fragments; out rows fetched via shfl ----
    #pragma unroll
    for (int mt = 0; mt < 2; ++mt) {
        const int src  = mt * 16 + (lane >> 2);
        const int om0  = __shfl_sync(0xffffffffu, om, src);
        const int om1  = __shfl_sync(0xffffffffu, om, src + 8);
        float* dst0 = out + (size_t)om0 * C_OUT + (lane & 3) * 2;
        float* dst1 = out + (size_t)om1 * C_OUT + (lane & 3) * 2;
        #pragma unroll
        for (int nt = 0; nt < 8; ++nt) {
            if (om0 >= 0)
                asm volatile("red.global.add.v2.f32 [%0], {%1,%2};"
                             :: "l"(dst0 + nt * 8), "f"(d[mt][nt][0]), "f"(d[mt][nt][1])
                             : "memory");
            if (om1 >= 0)
                asm volatile("red.global.add.v2.f32 [%0], {%1,%2};"
                             :: "l"(dst1 + nt * 8), "f"(d[mt][nt][2]), "f"(d[mt][nt][3])
                             : "memory");
        }
    }
}

// ---------------- BN stats --------------------------------------------------
__global__ void __launch_bounds__(256)
stats_kernel(const float* __restrict__ out)
{
    __shared__ float ss[256], sq[256];
    const int t = threadIdx.x, ch = t & 63, rep = t >> 6;
    float s = 0.f, q = 0.f;
    #pragma unroll 4
    for (int row = blockIdx.x * 4 + rep; row < N_OUTP; row += gridDim.x * 4) {
        const float v = out[(size_t)row * C_OUT + ch];
        s += v; q = fmaf(v, v, q);
    }
    ss[t] = s; sq[t] = q;
    __syncthreads();
    if (t < 64) {
        atomicAdd(&g_sum[t],   ss[t] + ss[t + 64] + ss[t + 128] + ss[t + 192]);
        atomicAdd(&g_sumsq[t], sq[t] + sq[t + 64] + sq[t + 128] + sq[t + 192]);
    }
}

// ---------------- normalize + ReLU (finalize folded in) ---------------------
__global__ void __launch_bounds__(256)
normalize_kernel(float* __restrict__ out,
                 const float* __restrict__ gamma,
                 const float* __restrict__ beta)
{
    __shared__ float sc[C_OUT], bs[C_OUT];
    if (threadIdx.x < C_OUT) {
        const int c = threadIdx.x;
        const float inv_n = 1.0f / (float)N_OUTP;
        const float mean = g_sum[c] * inv_n;
        const float var  = g_sumsq[c] * inv_n - mean * mean;
        const float s    = gamma[c] * rsqrtf(var + BN_EPS);
        sc[c] = s;
        bs[c] = beta[c] - mean * s;
    }
    __syncthreads();
    const int total4 = N_OUTP * C_OUT / 4;
    for (int i = blockIdx.x * blockDim.x + threadIdx.x; i < total4;
         i += gridDim.x * blockDim.x) {
        float4 v = ((float4*)out)[i];
        const int c0 = (i * 4) & 63;
        v.x = fmaxf(fmaf(v.x, sc[c0 + 0], bs[c0 + 0]), 0.f);
        v.y = fmaxf(fmaf(v.y, sc[c0 + 1], bs[c0 + 1]), 0.f);
        v.z = fmaxf(fmaf(v.z, sc[c0 + 2], bs[c0 + 2]), 0.f);
        v.w = fmaxf(fmaf(v.w, sc[c0 + 3], bs[c0 + 3]), 0.f);
        ((float4*)out)[i] = v;
    }
}

// ---------------- launch ----------------------------------------------------
extern "C" void kernel_launch(void* const* d_in, const int* in_sizes, int n_in,
                              void* d_out, int out_size)
{
    const float* x       = (const float*)d_in[0];
    const float* weight  = (const float*)d_in[1];
    const float* gamma   = (const float*)d_in[2];
    const float* beta    = (const float*)d_in[3];
    const int*   in_map  = (const int*)d_in[4];
    const int*   out_map = (const int*)d_in[5];
    float*       out     = (float*)d_out;

    cudaFuncSetAttribute(fused_kernel, cudaFuncAttributeMaxDynamicSharedMemorySize,
                         SMEM_FUSED);

    cudaMemsetAsync(out, 0, (size_t)out_size * sizeof(float));

    conv_x_kernel<<<(N_ROWS * 32 + 255) / 256, 256>>>(x);
    bfrag_kernel<<<(KOFF * 8 * 4 * 32 + 255) / 256, 256>>>(weight);

    {
        dim3 grid((M_PAIRS + PAIRS_BLK - 1) / PAIRS_BLK, KOFF);
        fused_kernel<<<grid, PAIRS_BLK, SMEM_FUSED>>>(in_map, out_map, out);
    }

    stats_kernel<<<1184, 256>>>(out);
    normalize_kernel<<<2048, 256>>>(out, gamma, beta);
}

// round 7
// speedup vs baseline: 1.3146x; 1.3146x over previous
#include <cuda_runtime.h>
#include <cuda_fp16.h>
#include <cstdint>

#define C_IN    128
#define C_OUT   64
#define KOFF    27
#define M_PAIRS 100000
#define N_ROWS  100000
#define N_OUTP  200000
#define BN_EPS  1e-5f

// ---------------- device scratch (allocation-free) --------------------------
__device__ __half g_Xh[(size_t)N_ROWS * C_IN];      // 25.6 MB, L2-resident
__device__ __half g_Wh[(size_t)KOFF * C_OUT * C_IN];// [k][co][ci], 0.44 MB
__device__ float g_sum[C_OUT], g_sumsq[C_OUT];

// ---------------- PTX helpers ----------------------------------------------
__device__ __forceinline__ uint32_t smem_u32(const void* p) {
    uint32_t a;
    asm("{ .reg .u64 t; cvta.to.shared.u64 t, %1; cvt.u32.u64 %0, t; }" : "=r"(a) : "l"(p));
    return a;
}
#define BULK_CP(dst, src, bytes, mbar) \
    asm volatile("cp.async.bulk.shared::cluster.global.mbarrier::complete_tx::bytes " \
        "[%0], [%1], %2, [%3];" :: "r"(dst), "l"(src), "r"(bytes), "r"(mbar) : "memory")

#define MBAR_INIT(a, c) \
    asm volatile("mbarrier.init.shared.b64 [%0], %1;" :: "r"(a), "r"(c) : "memory")
#define MBAR_EXPECT_TX(a, tx) \
    asm volatile("mbarrier.arrive.expect_tx.shared.b64 _, [%0], %1;" :: "r"(a), "r"(tx) : "memory")
#define MBAR_WAIT(a, ph) do {                                                   \
    asm volatile("{ .reg .pred P; WL%=:"                                        \
        " mbarrier.try_wait.parity.acquire.cta.shared::cta.b64 P, [%0], %1, 0x989680;" \
        " @P bra.uni WD%=; bra.uni WL%=; WD%=: }"                               \
        :: "r"(a), "r"(ph) : "memory");                                         \
} while (0)

#define LDMATRIX_X4(r, addr) \
    asm volatile("ldmatrix.sync.aligned.m8n8.x4.shared.b16 {%0,%1,%2,%3}, [%4];" \
        : "=r"((r)[0]), "=r"((r)[1]), "=r"((r)[2]), "=r"((r)[3]) : "r"(addr))

#define MMA16816(d, a, b0, b1) \
    asm volatile("mma.sync.aligned.m16n8k16.row.col.f32.f16.f16.f32 " \
        "{%0,%1,%2,%3}, {%4,%5,%6,%7}, {%8,%9}, {%0,%1,%2,%3};" \
        : "+f"((d)[0]), "+f"((d)[1]), "+f"((d)[2]), "+f"((d)[3]) \
        : "r"((a)[0]), "r"((a)[1]), "r"((a)[2]), "r"((a)[3]), "r"(b0), "r"(b1))

// ---------------- convert x -> fp16 -----------------------------------------
__global__ void __launch_bounds__(256)
conv_x_kernel(const float* __restrict__ x)
{
    int idx = blockIdx.x * 256 + threadIdx.x;          // one per 4 floats
    if (idx >= N_ROWS * 32) return;
    float4 v = ((const float4*)x)[idx];
    __half2* dst = (__half2*)(g_Xh + (size_t)idx * 4);
    dst[0] = __floats2half2_rn(v.x, v.y);
    dst[1] = __floats2half2_rn(v.z, v.w);
}

// ---------------- convert w -> fp16, transpose to [k][co][ci]; zero stats ---
__global__ void __launch_bounds__(256)
conv_w_kernel(const float* __restrict__ w)
{
    int idx = blockIdx.x * 256 + threadIdx.x;          // over 27*128*64
    if (idx < C_OUT) { g_sum[idx] = 0.f; g_sumsq[idx] = 0.f; }
    if (idx >= KOFF * C_IN * C_OUT) return;
    int k  = idx / (C_IN * C_OUT);
    int r  = idx % (C_IN * C_OUT);
    int ci = r / C_OUT, co = r % C_OUT;
    g_Wh[(size_t)k * (C_OUT * C_IN) + co * C_IN + ci] = __float2half_rn(w[idx]);
}

// ---------------- fused gather(bulk) + HMMA + direct-frag scatter -----------
// grid = (521 pair-blocks, 27 offsets); block = 192 threads (6 warps).
// Tile: 192 pairs x 64 out-channels, K = 128. Warp w owns rows [32w, 32w+32).
// Split barriers: bar0 = A rows 0..95 + B; bar1 = A rows 96..191 ->
// warps 0-2 start MMA while second half of gather is in flight.
// smem rows padded to 272 B -> ldmatrix conflict-free, no swizzle.
#define PAIRS_BLK 192
#define ROWB      272
#define SM_MBAR0  0
#define SM_MBAR1  8
#define SM_A      32
#define SM_B      (SM_A + PAIRS_BLK * ROWB)     // 52256
#define SMEM_FUSED (SM_B + 64 * ROWB)           // 69664

__global__ void __launch_bounds__(PAIRS_BLK)
fused_kernel(const int* __restrict__ in_map,
             const int* __restrict__ out_map,
             float* __restrict__ out)
{
    extern __shared__ char smem[];
    const uint32_t sbase = smem_u32(smem);
    const uint32_t abase = sbase + SM_A;
    const uint32_t bbase = sbase + SM_B;

    const int t    = threadIdx.x;
    const int lane = t & 31;
    const int w    = t >> 5;
    const int k    = blockIdx.y;

    // ---- pair indices (thread t owns pair-row t) ----
    const int p     = blockIdx.x * PAIRS_BLK + t;
    const int valid = (p < M_PAIRS);
    const int pc    = valid ? p : (M_PAIRS - 1);
    const int im    = in_map [k * M_PAIRS + pc];
    const int om    = valid ? out_map[k * M_PAIRS + pc] : -1;

    if (t == 0) { MBAR_INIT(sbase + SM_MBAR0, 1); MBAR_INIT(sbase + SM_MBAR1, 1); }
    __syncthreads();
    if (t == 0) MBAR_EXPECT_TX(sbase + SM_MBAR0, 96 * 256 + 64 * 256);
    if (t == 1) MBAR_EXPECT_TX(sbase + SM_MBAR1, 96 * 256);

    // ---- gather A: one 256B bulk per row; B rows by threads 0..63 ----
    const uint32_t mybar = sbase + (t < 96 ? SM_MBAR0 : SM_MBAR1);
    BULK_CP(abase + t * ROWB, g_Xh + (size_t)im * C_IN, 256, mybar);
    if (t < 64)
        BULK_CP(bbase + t * ROWB, g_Wh + ((size_t)k * C_OUT + t) * C_IN, 256,
                sbase + SM_MBAR0);

    MBAR_WAIT(sbase + SM_MBAR0, 0);
    if (w >= 3) MBAR_WAIT(sbase + SM_MBAR1, 0);

    // ---- MMA mainloop: warp w owns rows [32w, 32w+32), cols 0..63 ----
    float d[2][8][4];
    #pragma unroll
    for (int mt = 0; mt < 2; ++mt)
        #pragma unroll
        for (int nt = 0; nt < 8; ++nt)
            #pragma unroll
            for (int j = 0; j < 4; ++j) d[mt][nt][j] = 0.f;

    #pragma unroll
    for (int kc = 0; kc < 8; ++kc) {
        uint32_t a_frag[2][4];
        #pragma unroll
        for (int mt = 0; mt < 2; ++mt) {
            int row = w * 32 + mt * 16 + (lane & 15);
            int ch  = kc * 2 + (lane >> 4);
            LDMATRIX_X4(a_frag[mt], abase + row * ROWB + ch * 16);
        }
        uint32_t b_frag[4][4];
        #pragma unroll
        for (int nt2 = 0; nt2 < 4; ++nt2) {
            int n  = nt2 * 16 + ((lane >> 4) << 3) + (lane & 7);
            int ch = kc * 2 + ((lane >> 3) & 1);
            LDMATRIX_X4(b_frag[nt2], bbase + n * ROWB + ch * 16);
        }
        #pragma unroll
        for (int mt = 0; mt < 2; ++mt)
            #pragma unroll
            for (int nt = 0; nt < 8; ++nt)
                MMA16816(d[mt][nt], a_frag[mt],
                         b_frag[nt >> 1][(nt & 1) * 2],
                         b_frag[nt >> 1][(nt & 1) * 2 + 1]);
    }

    // ---- scatter-add straight from fragments; out rows fetched via shfl ----
    // fragment (mt, nt): rows r = mt*16+(lane>>2) (+8) within this warp;
    // 4 lanes with equal lane>>2 cover one contiguous 32B sector of one row.
    #pragma unroll
    for (int mt = 0; mt < 2; ++mt) {
        const int src  = mt * 16 + (lane >> 2);
        const int om0  = __shfl_sync(0xffffffffu, om, src);
        const int om1  = __shfl_sync(0xffffffffu, om, src + 8);
        float* dst0 = out + (size_t)om0 * C_OUT + (lane & 3) * 2;
        float* dst1 = out + (size_t)om1 * C_OUT + (lane & 3) * 2;
        #pragma unroll
        for (int nt = 0; nt < 8; ++nt) {
            if (om0 >= 0)
                asm volatile("red.global.add.v2.f32 [%0], {%1,%2};"
                             :: "l"(dst0 + nt * 8), "f"(d[mt][nt][0]), "f"(d[mt][nt][1])
                             : "memory");
            if (om1 >= 0)
                asm volatile("red.global.add.v2.f32 [%0], {%1,%2};"
                             :: "l"(dst1 + nt * 8), "f"(d[mt][nt][2]), "f"(d[mt][nt][3])
                             : "memory");
        }
    }
}

// ---------------- BN stats (float4 loads: thread owns 4 channels) -----------
__global__ void __launch_bounds__(256)
stats_kernel(const float* __restrict__ out)
{
    __shared__ float ss[256], sq[256];
    const int t   = threadIdx.x;
    const int c4  = (t & 15) * 4;                 // channel group (16 groups)
    const int rep = t >> 4;                       // 16 row-replicas per block
    float4 s = make_float4(0.f, 0.f, 0.f, 0.f);
    float4 q = make_float4(0.f, 0.f, 0.f, 0.f);
    #pragma unroll 2
    for (int row = blockIdx.x * 16 + rep; row < N_OUTP; row += gridDim.x * 16) {
        const float4 v = *(const float4*)(out + (size_t)row * C_OUT + c4);
        s.x += v.x; q.x = fmaf(v.x, v.x, q.x);
        s.y += v.y; q.y = fmaf(v.y, v.y, q.y);
        s.z += v.z; q.z = fmaf(v.z, v.z, q.z);
        s.w += v.w; q.w = fmaf(v.w, v.w, q.w);
    }
    // smem layout: partial[rep][channel]; reduce reps 16..1 via strided adds
    // store 4 channels per thread at ss[rep*? ] -> use ss[t] with channel major:
    // index = (t&15)*4 + comp gives channel; rep dim folded by atomic smem-free tree.
    // Simpler: each thread writes its 4 sums into 4 slots of a 64x? -- use two
    // rounds: first lane-level, then cross-rep via shared.
    ss[t] = s.x; sq[t] = q.x;
    __syncthreads();
    // reduce across reps for component x, then rotate components through smem
    float accs[4], accq[4];
    #pragma unroll
    for (int comp = 0; comp < 4; ++comp) {
        if (comp) {
            __syncthreads();
            ss[t] = comp == 1 ? s.y : (comp == 2 ? s.z : s.w);
            sq[t] = comp == 1 ? q.y : (comp == 2 ? q.z : q.w);
            __syncthreads();
        }
        if (t < 16) {
            float rs = 0.f, rq = 0.f;
            #pragma unroll
            for (int r = 0; r < 16; ++r) { rs += ss[r * 16 + t]; rq += sq[r * 16 + t]; }
            accs[comp] = rs; accq[comp] = rq;
        }
    }
    if (t < 16) {
        #pragma unroll
        for (int comp = 0; comp < 4; ++comp) {
            atomicAdd(&g_sum[t * 4 + comp],   accs[comp]);
            atomicAdd(&g_sumsq[t * 4 + comp], accq[comp]);
        }
    }
}

// ---------------- normalize + ReLU (finalize folded in) ---------------------
__global__ void __launch_bounds__(256)
normalize_kernel(float* __restrict__ out,
                 const float* __restrict__ gamma,
                 const float* __restrict__ beta)
{
    __shared__ float sc[C_OUT], bs[C_OUT];
    if (threadIdx.x < C_OUT) {
        const int c = threadIdx.x;
        const float inv_n = 1.0f / (float)N_OUTP;
        const float mean = g_sum[c] * inv_n;
        const float var  = g_sumsq[c] * inv_n - mean * mean;
        const float s    = gamma[c] * rsqrtf(var + BN_EPS);
        sc[c] = s;
        bs[c] = beta[c] - mean * s;
    }
    __syncthreads();
    const int total4 = N_OUTP * C_OUT / 4;
    for (int i = blockIdx.x * blockDim.x + threadIdx.x; i < total4;
         i += gridDim.x * blockDim.x) {
        float4 v = ((float4*)out)[i];
        const int c0 = (i * 4) & 63;
        v.x = fmaxf(fmaf(v.x, sc[c0 + 0], bs[c0 + 0]), 0.f);
        v.y = fmaxf(fmaf(v.y, sc[c0 + 1], bs[c0 + 1]), 0.f);
        v.z = fmaxf(fmaf(v.z, sc[c0 + 2], bs[c0 + 2]), 0.f);
        v.w = fmaxf(fmaf(v.w, sc[c0 + 3], bs[c0 + 3]), 0.f);
        ((float4*)out)[i] = v;
    }
}

// ---------------- launch ----------------------------------------------------
extern "C" void kernel_launch(void* const* d_in, const int* in_sizes, int n_in,
                              void* d_out, int out_size)
{
    const float* x       = (const float*)d_in[0];
    const float* weight  = (const float*)d_in[1];
    const float* gamma   = (const float*)d_in[2];
    const float* beta    = (const float*)d_in[3];
    const int*   in_map  = (const int*)d_in[4];
    const int*   out_map = (const int*)d_in[5];
    float*       out     = (float*)d_out;

    cudaFuncSetAttribute(fused_kernel, cudaFuncAttributeMaxDynamicSharedMemorySize,
                         SMEM_FUSED);

    cudaMemsetAsync(out, 0, (size_t)out_size * sizeof(float));

    conv_x_kernel<<<(N_ROWS * 32 + 255) / 256, 256>>>(x);
    conv_w_kernel<<<(KOFF * C_IN * C_OUT + 255) / 256, 256>>>(weight);

    {
        dim3 grid((M_PAIRS + PAIRS_BLK - 1) / PAIRS_BLK, KOFF);
        fused_kernel<<<grid, PAIRS_BLK, SMEM_FUSED>>>(in_map, out_map, out);
    }

    stats_kernel<<<1184, 256>>>(out);
    normalize_kernel<<<2048, 256>>>(out, gamma, beta);
}

// round 8
// speedup vs baseline: 1.4615x; 1.1118x over previous
#include <cuda_runtime.h>
#include <cuda_fp16.h>
#include <cstdint>

#define C_IN    128
#define C_OUT   64
#define KOFF    27
#define M_PAIRS 100000
#define N_ROWS  100000
#define N_OUTP  200000
#define BN_EPS  1e-5f

// ---------------- device scratch (allocation-free) --------------------------
__device__ __half g_Xh[(size_t)N_ROWS * C_IN];      // 25.6 MB, L2-resident
__device__ __half g_Wh[(size_t)KOFF * C_OUT * C_IN];// [k][co][ci], 0.44 MB
__device__ float g_sum[C_OUT], g_sumsq[C_OUT];

// ---------------- PTX helpers ----------------------------------------------
__device__ __forceinline__ uint32_t smem_u32(const void* p) {
    uint32_t a;
    asm("{ .reg .u64 t; cvta.to.shared.u64 t, %1; cvt.u32.u64 %0, t; }" : "=r"(a) : "l"(p));
    return a;
}
#define BULK_CP(dst, src, bytes, mbar) \
    asm volatile("cp.async.bulk.shared::cluster.global.mbarrier::complete_tx::bytes " \
        "[%0], [%1], %2, [%3];" :: "r"(dst), "l"(src), "r"(bytes), "r"(mbar) : "memory")

#define MBAR_INIT(a, c) \
    asm volatile("mbarrier.init.shared.b64 [%0], %1;" :: "r"(a), "r"(c) : "memory")
#define MBAR_EXPECT_TX(a, tx) \
    asm volatile("mbarrier.arrive.expect_tx.shared.b64 _, [%0], %1;" :: "r"(a), "r"(tx) : "memory")
#define MBAR_WAIT(a, ph) do {                                                   \
    asm volatile("{ .reg .pred P; WL%=:"                                        \
        " mbarrier.try_wait.parity.acquire.cta.shared::cta.b64 P, [%0], %1, 0x989680;" \
        " @P bra.uni WD%=; bra.uni WL%=; WD%=: }"                               \
        :: "r"(a), "r"(ph) : "memory");                                         \
} while (0)

#define LDMATRIX_X4(r, addr) \
    asm volatile("ldmatrix.sync.aligned.m8n8.x4.shared.b16 {%0,%1,%2,%3}, [%4];" \
        : "=r"((r)[0]), "=r"((r)[1]), "=r"((r)[2]), "=r"((r)[3]) : "r"(addr))

#define MMA16816(d, a, b0, b1) \
    asm volatile("mma.sync.aligned.m16n8k16.row.col.f32.f16.f16.f32 " \
        "{%0,%1,%2,%3}, {%4,%5,%6,%7}, {%8,%9}, {%0,%1,%2,%3};" \
        : "+f"((d)[0]), "+f"((d)[1]), "+f"((d)[2]), "+f"((d)[3]) \
        : "r"((a)[0]), "r"((a)[1]), "r"((a)[2]), "r"((a)[3]), "r"(b0), "r"(b1))

// ---------------- prep: x->fp16 + zero out | w->fp16(T) + zero stats --------
// blocks [0, 12500): idx = gid*256+t in [0, 3.2M): convert one x float4 AND
// zero the matching float4 of out (3.2M float4 == 12.8M floats == out size).
// blocks [12500, 13364): convert w (27*128*64 = 221184 elems) + zero stats.
#define XBLKS 12500

__global__ void __launch_bounds__(256)
prep_kernel(const float* __restrict__ x,
            const float* __restrict__ w,
            float* __restrict__ out,
            int out_n4)
{
    const int gid = blockIdx.x;
    if (gid < XBLKS) {
        const int idx = gid * 256 + threadIdx.x;
        float4 v = ((const float4*)x)[idx];
        __half2* dst = (__half2*)(g_Xh + (size_t)idx * 4);
        dst[0] = __floats2half2_rn(v.x, v.y);
        dst[1] = __floats2half2_rn(v.z, v.w);
        if (idx < out_n4)
            ((float4*)out)[idx] = make_float4(0.f, 0.f, 0.f, 0.f);
    } else {
        const int j = (gid - XBLKS) * 256 + threadIdx.x;
        if (j < C_OUT) { g_sum[j] = 0.f; g_sumsq[j] = 0.f; }
        if (j < KOFF * C_IN * C_OUT) {
            const int k  = j / (C_IN * C_OUT);
            const int r  = j % (C_IN * C_OUT);
            const int ci = r / C_OUT, co = r % C_OUT;
            g_Wh[(size_t)k * (C_OUT * C_IN) + co * C_IN + ci] = __float2half_rn(w[j]);
        }
    }
}

// ---------------- fused gather(bulk) + HMMA + direct-frag scatter -----------
// grid = (521 pair-blocks, 27 offsets); block = 192 threads (6 warps).
// Tile: 192 pairs x 64 out-channels, K = 128. Warp w owns rows [32w, 32w+32).
// Split barriers: bar0 = A rows 0..95 + B; bar1 = A rows 96..191 ->
// warps 0-2 start MMA while second half of gather is in flight.
// smem rows padded to 272 B -> ldmatrix conflict-free, no swizzle.
#define PAIRS_BLK 192
#define ROWB      272
#define SM_MBAR0  0
#define SM_MBAR1  8
#define SM_A      32
#define SM_B      (SM_A + PAIRS_BLK * ROWB)     // 52256
#define SMEM_FUSED (SM_B + 64 * ROWB)           // 69664

__global__ void __launch_bounds__(PAIRS_BLK)
fused_kernel(const int* __restrict__ in_map,
             const int* __restrict__ out_map,
             float* __restrict__ out)
{
    extern __shared__ char smem[];
    const uint32_t sbase = smem_u32(smem);
    const uint32_t abase = sbase + SM_A;
    const uint32_t bbase = sbase + SM_B;

    const int t    = threadIdx.x;
    const int lane = t & 31;
    const int w    = t >> 5;
    const int k    = blockIdx.y;

    // ---- pair indices (thread t owns pair-row t) ----
    const int p     = blockIdx.x * PAIRS_BLK + t;
    const int valid = (p < M_PAIRS);
    const int pc    = valid ? p : (M_PAIRS - 1);
    const int im    = in_map [k * M_PAIRS + pc];
    const int om    = valid ? out_map[k * M_PAIRS + pc] : -1;

    if (t == 0) { MBAR_INIT(sbase + SM_MBAR0, 1); MBAR_INIT(sbase + SM_MBAR1, 1); }
    __syncthreads();
    if (t == 0) MBAR_EXPECT_TX(sbase + SM_MBAR0, 96 * 256 + 64 * 256);
    if (t == 1) MBAR_EXPECT_TX(sbase + SM_MBAR1, 96 * 256);

    // ---- gather A: one 256B bulk per row; B rows by threads 0..63 ----
    const uint32_t mybar = sbase + (t < 96 ? SM_MBAR0 : SM_MBAR1);
    BULK_CP(abase + t * ROWB, g_Xh + (size_t)im * C_IN, 256, mybar);
    if (t < 64)
        BULK_CP(bbase + t * ROWB, g_Wh + ((size_t)k * C_OUT + t) * C_IN, 256,
                sbase + SM_MBAR0);

    MBAR_WAIT(sbase + SM_MBAR0, 0);
    if (w >= 3) MBAR_WAIT(sbase + SM_MBAR1, 0);

    // ---- MMA mainloop: warp w owns rows [32w, 32w+32), cols 0..63 ----
    float d[2][8][4];
    #pragma unroll
    for (int mt = 0; mt < 2; ++mt)
        #pragma unroll
        for (int nt = 0; nt < 8; ++nt)
            #pragma unroll
            for (int j = 0; j < 4; ++j) d[mt][nt][j] = 0.f;

    #pragma unroll
    for (int kc = 0; kc < 8; ++kc) {
        uint32_t a_frag[2][4];
        #pragma unroll
        for (int mt = 0; mt < 2; ++mt) {
            int row = w * 32 + mt * 16 + (lane & 15);
            int ch  = kc * 2 + (lane >> 4);
            LDMATRIX_X4(a_frag[mt], abase + row * ROWB + ch * 16);
        }
        uint32_t b_frag[4][4];
        #pragma unroll
        for (int nt2 = 0; nt2 < 4; ++nt2) {
            int n  = nt2 * 16 + ((lane >> 4) << 3) + (lane & 7);
            int ch = kc * 2 + ((lane >> 3) & 1);
            LDMATRIX_X4(b_frag[nt2], bbase + n * ROWB + ch * 16);
        }
        #pragma unroll
        for (int mt = 0; mt < 2; ++mt)
            #pragma unroll
            for (int nt = 0; nt < 8; ++nt)
                MMA16816(d[mt][nt], a_frag[mt],
                         b_frag[nt >> 1][(nt & 1) * 2],
                         b_frag[nt >> 1][(nt & 1) * 2 + 1]);
    }

    // ---- scatter-add straight from fragments; out rows fetched via shfl ----
    // fragment (mt, nt): rows r = mt*16+(lane>>2) (+8) within this warp;
    // 4 lanes with equal lane>>2 cover one contiguous 32B sector of one row.
    #pragma unroll
    for (int mt = 0; mt < 2; ++mt) {
        const int src  = mt * 16 + (lane >> 2);
        const int om0  = __shfl_sync(0xffffffffu, om, src);
        const int om1  = __shfl_sync(0xffffffffu, om, src + 8);
        float* dst0 = out + (size_t)om0 * C_OUT + (lane & 3) * 2;
        float* dst1 = out + (size_t)om1 * C_OUT + (lane & 3) * 2;
        #pragma unroll
        for (int nt = 0; nt < 8; ++nt) {
            if (om0 >= 0)
                asm volatile("red.global.add.v2.f32 [%0], {%1,%2};"
                             :: "l"(dst0 + nt * 8), "f"(d[mt][nt][0]), "f"(d[mt][nt][1])
                             : "memory");
            if (om1 >= 0)
                asm volatile("red.global.add.v2.f32 [%0], {%1,%2};"
                             :: "l"(dst1 + nt * 8), "f"(d[mt][nt][2]), "f"(d[mt][nt][3])
                             : "memory");
        }
    }
}

// ---------------- BN stats (R5-proven scalar form) --------------------------
__global__ void __launch_bounds__(256)
stats_kernel(const float* __restrict__ out)
{
    __shared__ float ss[256], sq[256];
    const int t = threadIdx.x, ch = t & 63, rep = t >> 6;
    float s = 0.f, q = 0.f;
    #pragma unroll 4
    for (int row = blockIdx.x * 4 + rep; row < N_OUTP; row += gridDim.x * 4) {
        const float v = out[(size_t)row * C_OUT + ch];
        s += v; q = fmaf(v, v, q);
    }
    ss[t] = s; sq[t] = q;
    __syncthreads();
    if (t < 64) {
        atomicAdd(&g_sum[t],   ss[t] + ss[t + 64] + ss[t + 128] + ss[t + 192]);
        atomicAdd(&g_sumsq[t], sq[t] + sq[t + 64] + sq[t + 128] + sq[t + 192]);
    }
}

// ---------------- normalize + ReLU (finalize folded in) ---------------------
__global__ void __launch_bounds__(256)
normalize_kernel(float* __restrict__ out,
                 const float* __restrict__ gamma,
                 const float* __restrict__ beta)
{
    __shared__ float sc[C_OUT], bs[C_OUT];
    if (threadIdx.x < C_OUT) {
        const int c = threadIdx.x;
        const float inv_n = 1.0f / (float)N_OUTP;
        const float mean = g_sum[c] * inv_n;
        const float var  = g_sumsq[c] * inv_n - mean * mean;
        const float s    = gamma[c] * rsqrtf(var + BN_EPS);
        sc[c] = s;
        bs[c] = beta[c] - mean * s;
    }
    __syncthreads();
    const int total4 = N_OUTP * C_OUT / 4;
    for (int i = blockIdx.x * blockDim.x + threadIdx.x; i < total4;
         i += gridDim.x * blockDim.x) {
        float4 v = ((float4*)out)[i];
        const int c0 = (i * 4) & 63;
        v.x = fmaxf(fmaf(v.x, sc[c0 + 0], bs[c0 + 0]), 0.f);
        v.y = fmaxf(fmaf(v.y, sc[c0 + 1], bs[c0 + 1]), 0.f);
        v.z = fmaxf(fmaf(v.z, sc[c0 + 2], bs[c0 + 2]), 0.f);
        v.w = fmaxf(fmaf(v.w, sc[c0 + 3], bs[c0 + 3]), 0.f);
        ((float4*)out)[i] = v;
    }
}

// ---------------- launch ----------------------------------------------------
extern "C" void kernel_launch(void* const* d_in, const int* in_sizes, int n_in,
                              void* d_out, int out_size)
{
    const float* x       = (const float*)d_in[0];
    const float* weight  = (const float*)d_in[1];
    const float* gamma   = (const float*)d_in[2];
    const float* beta    = (const float*)d_in[3];
    const int*   in_map  = (const int*)d_in[4];
    const int*   out_map = (const int*)d_in[5];
    float*       out     = (float*)d_out;

    cudaFuncSetAttribute(fused_kernel, cudaFuncAttributeMaxDynamicSharedMemorySize,
                         SMEM_FUSED);

    const int wblks = (KOFF * C_IN * C_OUT + 255) / 256;       // 864
    prep_kernel<<<XBLKS + wblks, 256>>>(x, weight, out, out_size / 4);

    {
        dim3 grid((M_PAIRS + PAIRS_BLK - 1) / PAIRS_BLK, KOFF);
        fused_kernel<<<grid, PAIRS_BLK, SMEM_FUSED>>>(in_map, out_map, out);
    }

    stats_kernel<<<1184, 256>>>(out);
    normalize_kernel<<<2048, 256>>>(out, gamma, beta);
}